// round 6
// baseline (speedup 1.0000x reference)
#include <cuda_runtime.h>
#include <math.h>

// Problem constants: B=4, n=4096 points, m=512 triangles.
#define BATCH 4
#define NPTS  4096
#define MTRI  512
#define BN    (BATCH * NPTS)   // 16384

// Decomposition: 64-thread CTAs (2 warps), 8 points/CTA, grid = 2048.
//   chunk = tid & 31 (32 triangle chunks), quad = tid >> 5 (2 point-quads).
//   Each thread: 4 points x 16 triangles (t = j*32 + chunk).
//   Small CTAs -> ~12 resident/SM, 13.8 CTAs per SM over the run -> no wave tail.
// Algebra (d3=d1-e1, d4=d2-e2, d5=d1-e2, d6=d2-e3):
//   vc = e1*d2 - e2*d1,  vb = e3*d1 - e2*d2,  va = denom - vb - vc,
//   denom = e1*e3 - e2^2 and |cb|^2 = e1-2e2+e3 are per-triangle constants.
//   All regions share one denominator D -> single rcp per eval.
// Gram terms recomputed in registers per triangle (amortized over 4 points) —
// NOT stored in smem (round-5 regression: extra LDS cost > recompute cost).
// Region code recomputed reference-exactly for the winning triangle only.

__device__ __forceinline__ float frcp(float x) {
    float r;
    asm("rcp.approx.f32 %0, %1;" : "=f"(r) : "f"(x));
    return r;
}

__device__ int region_of(float px, float py, float pz,
                         float ax, float ay, float az,
                         float bx, float by, float bz,
                         float cx, float cy, float cz)
{
    const float abx = bx - ax, aby = by - ay, abz = bz - az;
    const float acx = cx - ax, acy = cy - ay, acz = cz - az;
    const float apx = px - ax, apy = py - ay, apz = pz - az;
    const float bpx = px - bx, bpy = py - by, bpz = pz - bz;
    const float cpx = px - cx, cpy = py - cy, cpz = pz - cz;
    const float d1 = abx * apx + aby * apy + abz * apz;
    const float d2 = acx * apx + acy * apy + acz * apz;
    const float d3 = abx * bpx + aby * bpy + abz * bpz;
    const float d4 = acx * bpx + acy * bpy + acz * bpz;
    const float d5 = abx * cpx + aby * cpy + abz * cpz;
    const float d6 = acx * cpx + acy * cpy + acz * cpz;
    const float vc = d1 * d4 - d3 * d2;
    const float vb = d5 * d2 - d1 * d6;
    const float va = d3 * d6 - d5 * d4;
    if (d1 <= 0.f && d2 <= 0.f) return 0;
    if (d3 >= 0.f && d4 <= d3) return 1;
    if (vc <= 0.f && d1 >= 0.f && d3 <= 0.f) return 3;
    if (d6 >= 0.f && d5 <= d6) return 2;
    if (vb <= 0.f && d2 >= 0.f && d6 <= 0.f) return 4;
    if (va <= 0.f && (d4 - d3) >= 0.f && (d5 - d6) >= 0.f) return 5;
    return 6;
}

__global__ void __launch_bounds__(64, 12)
tridist_kernel(const float* __restrict__ xyz,
               const float* __restrict__ tri1,
               const float* __restrict__ tri2,
               const float* __restrict__ tri3,
               float* __restrict__ out)
{
    __shared__ float sm[9][MTRI];   // ax ay az bx by bz cx cy cz  (SoA)
    __shared__ float sp[24];        // 8 points * 3

    const int b     = blockIdx.x >> 9;           // 512 CTAs per batch
    const int blk   = blockIdx.x & 511;
    const int pbase = b * NPTS + blk * 8;

    // Stage triangles (float4 loads, SoA scatter into smem).
    {
        const float4* t1 = (const float4*)(tri1 + b * MTRI * 3);
        const float4* t2 = (const float4*)(tri2 + b * MTRI * 3);
        const float4* t3 = (const float4*)(tri3 + b * MTRI * 3);
        #pragma unroll
        for (int it = 0; it < 6; ++it) {
            const int i4 = it * 64 + threadIdx.x;    // 0..383
            float4 v1 = t1[i4], v2 = t2[i4], v3 = t3[i4];
            const int base = i4 * 4;
            float f1[4] = {v1.x, v1.y, v1.z, v1.w};
            float f2[4] = {v2.x, v2.y, v2.z, v2.w};
            float f3[4] = {v3.x, v3.y, v3.z, v3.w};
            #pragma unroll
            for (int e = 0; e < 4; ++e) {
                const int idx = base + e;
                const int j = idx / 3;
                const int k = idx - j * 3;
                sm[k    ][j] = f1[e];
                sm[3 + k][j] = f2[e];
                sm[6 + k][j] = f3[e];
            }
        }
        if (threadIdx.x < 24) sp[threadIdx.x] = xyz[pbase * 3 + threadIdx.x];
    }
    __syncthreads();

    const int chunk = threadIdx.x & 31;
    const int quad  = threadIdx.x >> 5;   // 0..1

    float px[4], py[4], pz[4];
    float bestD[4];
    int   bestT[4];
    #pragma unroll
    for (int k = 0; k < 4; ++k) {
        px[k] = sp[(quad * 4 + k) * 3 + 0];
        py[k] = sp[(quad * 4 + k) * 3 + 1];
        pz[k] = sp[(quad * 4 + k) * 3 + 2];
        bestD[k] = INFINITY;
        bestT[k] = 0x7fffffff;
    }

    #pragma unroll 2
    for (int j = 0; j < 16; ++j) {
        const int t = j * 32 + chunk;

        const float ax = sm[0][t], ay = sm[1][t], az = sm[2][t];
        const float bx = sm[3][t], by = sm[4][t], bz = sm[5][t];
        const float cx = sm[6][t], cy = sm[7][t], cz = sm[8][t];

        // per-triangle terms, amortized over 4 points (registers, not smem)
        const float abx = bx - ax, aby = by - ay, abz = bz - az;
        const float acx = cx - ax, acy = cy - ay, acz = cz - az;
        const float e1 = fmaf(abx, abx, fmaf(aby, aby, abz * abz));
        const float e2 = fmaf(abx, acx, fmaf(aby, acy, abz * acz));
        const float e3 = fmaf(acx, acx, fmaf(acy, acy, acz * acz));
        const float f1  = e1 - e2;
        const float f2  = e3 - e2;
        const float cb2 = f1 + f2;                      // |cb|^2
        const float denom = fmaf(e1, e3, -(e2 * e2));   // = va+vb+vc

        #pragma unroll
        for (int k = 0; k < 4; ++k) {
            const float apx = px[k] - ax, apy = py[k] - ay, apz = pz[k] - az;
            const float d1 = fmaf(abx, apx, fmaf(aby, apy, abz * apz));
            const float d2 = fmaf(acx, apx, fmaf(acy, apy, acz * apz));

            const float g  = d2 - d1;
            const float u1 = g + f1;          // = d4 - d3
            const float u2 = f2 - g;          // = d5 - d6
            const float vb = fmaf(e3, d1, -(e2 * d2));
            const float vc = fmaf(e1, d2, -(e2 * d1));
            const float va = denom - vb - vc;

            // priority: a > b > ab > c > ac > bc > face
            const bool ca  = (d1 <= 0.f) & (d2 <= 0.f);
            const bool cbv = (d1 >= e1) & (u1 <= 0.f);
            const bool cab = (vc <= 0.f) & (d1 >= 0.f) & (d1 <= e1);
            const bool ccv = (d2 >= e3) & (u2 <= 0.f);
            const bool cac = (vb <= 0.f) & (d2 >= 0.f) & (d2 <= e3);
            const bool cbc = (va <= 0.f) & (u1 >= 0.f) & (u2 >= 0.f);

            // Common-denominator select (reverse priority application):
            //   region:   face   bc    ac   c    ab   b    a
            //   n1 (v):   vb     u2    0    0    d1   1    0
            //   n2 (w):   vc     u1    d2   1    0    0    0
            //   D:        denom  cb2   e3   1    e1   1    1
            float n1 = vb;
            n1 = cbc ? u2 : n1;
            n1 = (cac | ccv) ? 0.f : n1;
            n1 = cab ? d1 : n1;
            n1 = cbv ? 1.f : n1;
            n1 = ca  ? 0.f : n1;

            float n2 = vc;
            n2 = cbc ? u1 : n2;
            n2 = cac ? d2 : n2;
            n2 = ccv ? 1.f : n2;
            n2 = (cab | cbv | ca) ? 0.f : n2;

            float D = denom;
            D = cbc ? cb2 : D;
            D = cac ? e3  : D;
            D = ccv ? 1.f : D;
            D = cab ? e1  : D;
            D = (cbv | ca) ? 1.f : D;

            const float rD = frcp(D);   // rcp(1.0) == 1.0 exactly
            const float v = n1 * rD;
            const float w = n2 * rD;

            const float qx = fmaf(v, abx, fmaf(w, acx, ax));
            const float qy = fmaf(v, aby, fmaf(w, acy, ay));
            const float qz = fmaf(v, abz, fmaf(w, acz, az));

            const float dx = px[k] - qx, dy = py[k] - qy, dz = pz[k] - qz;
            const float d2s = fmaf(dx, dx, fmaf(dy, dy, dz * dz));

            if (d2s < bestD[k]) {   // t strictly increases -> first-win ok
                bestD[k] = d2s;
                bestT[k] = t;
            }
        }
    }

    // Lexicographic (dist, index) butterfly reduction across the 32 chunks.
    #pragma unroll
    for (int off = 1; off < 32; off <<= 1) {
        #pragma unroll
        for (int k = 0; k < 4; ++k) {
            float dO = __shfl_xor_sync(0xffffffffu, bestD[k], off);
            int   tO = __shfl_xor_sync(0xffffffffu, bestT[k], off);
            if (dO < bestD[k] || (dO == bestD[k] && tO < bestT[k])) {
                bestD[k] = dO;
                bestT[k] = tO;
            }
        }
    }

    if (chunk == 0) {
        #pragma unroll
        for (int k = 0; k < 4; ++k) {
            const int g = pbase + quad * 4 + k;
            const int t = bestT[k];
            const int r = region_of(px[k], py[k], pz[k],
                                    sm[0][t], sm[1][t], sm[2][t],
                                    sm[3][t], sm[4][t], sm[5][t],
                                    sm[6][t], sm[7][t], sm[8][t]);
            out[g]          = bestD[k];
            out[BN + g]     = (float)r;
            out[2 * BN + g] = (float)t;
        }
    }
}

extern "C" void kernel_launch(void* const* d_in, const int* in_sizes, int n_in,
                              void* d_out, int out_size)
{
    const float* xyz  = (const float*)d_in[0];
    const float* tri1 = (const float*)d_in[1];
    const float* tri2 = (const float*)d_in[2];
    const float* tri3 = (const float*)d_in[3];
    float* out = (float*)d_out;

    dim3 grid(BN / 8);    // 2048 CTAs
    dim3 block(64);
    tridist_kernel<<<grid, block>>>(xyz, tri1, tri2, tri3, out);
}

// round 7
// speedup vs baseline: 1.2783x; 1.2783x over previous
#include <cuda_runtime.h>
#include <math.h>

// Problem constants: B=4, n=4096 points, m=512 triangles.
#define BATCH 4
#define NPTS  4096
#define MTRI  512
#define BN    (BATCH * NPTS)   // 16384

// Decomposition (round-4 proven shape): 128-thread CTAs, 16 points/CTA,
// grid = 1024. chunk = tid & 31 (32 triangle chunks), quad = tid >> 5.
// Each thread: 4 points x 16 triangles (t = j*32 + chunk).
//
// Candidate-min formulation (replaces the Ericson region cascade):
//   dist^2 = min(seg_ab, seg_ac, seg_bc, inside ? face : +inf)
// Each candidate uses an explicit difference vector (no cancellation).
// Independent candidates -> wide ILP, no serial select chains.
// Region code recomputed reference-exactly for the winning triangle only.

__device__ __forceinline__ float frcp(float x) {
    float r;
    asm("rcp.approx.f32 %0, %1;" : "=f"(r) : "f"(x));
    return r;
}

__device__ int region_of(float px, float py, float pz,
                         float ax, float ay, float az,
                         float bx, float by, float bz,
                         float cx, float cy, float cz)
{
    const float abx = bx - ax, aby = by - ay, abz = bz - az;
    const float acx = cx - ax, acy = cy - ay, acz = cz - az;
    const float apx = px - ax, apy = py - ay, apz = pz - az;
    const float bpx = px - bx, bpy = py - by, bpz = pz - bz;
    const float cpx = px - cx, cpy = py - cy, cpz = pz - cz;
    const float d1 = abx * apx + aby * apy + abz * apz;
    const float d2 = acx * apx + acy * apy + acz * apz;
    const float d3 = abx * bpx + aby * bpy + abz * bpz;
    const float d4 = acx * bpx + acy * bpy + acz * bpz;
    const float d5 = abx * cpx + aby * cpy + abz * cpz;
    const float d6 = acx * cpx + acy * cpy + acz * cpz;
    const float vc = d1 * d4 - d3 * d2;
    const float vb = d5 * d2 - d1 * d6;
    const float va = d3 * d6 - d5 * d4;
    if (d1 <= 0.f && d2 <= 0.f) return 0;
    if (d3 >= 0.f && d4 <= d3) return 1;
    if (vc <= 0.f && d1 >= 0.f && d3 <= 0.f) return 3;
    if (d6 >= 0.f && d5 <= d6) return 2;
    if (vb <= 0.f && d2 >= 0.f && d6 <= 0.f) return 4;
    if (va <= 0.f && (d4 - d3) >= 0.f && (d5 - d6) >= 0.f) return 5;
    return 6;
}

__global__ void __launch_bounds__(128, 6)
tridist_kernel(const float* __restrict__ xyz,
               const float* __restrict__ tri1,
               const float* __restrict__ tri2,
               const float* __restrict__ tri3,
               float* __restrict__ out)
{
    __shared__ float sm[9][MTRI];   // ax ay az bx by bz cx cy cz  (SoA)
    __shared__ float sp[48];        // 16 points * 3

    const int b     = blockIdx.x >> 8;
    const int blk   = blockIdx.x & 255;
    const int pbase = b * NPTS + blk * 16;

    // Stage triangles (float4 loads, SoA scatter into smem).
    {
        const float4* t1 = (const float4*)(tri1 + b * MTRI * 3);
        const float4* t2 = (const float4*)(tri2 + b * MTRI * 3);
        const float4* t3 = (const float4*)(tri3 + b * MTRI * 3);
        #pragma unroll
        for (int it = 0; it < 3; ++it) {
            const int i4 = it * 128 + threadIdx.x;   // 0..383
            float4 v1 = t1[i4], v2 = t2[i4], v3 = t3[i4];
            const int base = i4 * 4;
            float f1[4] = {v1.x, v1.y, v1.z, v1.w};
            float f2[4] = {v2.x, v2.y, v2.z, v2.w};
            float f3[4] = {v3.x, v3.y, v3.z, v3.w};
            #pragma unroll
            for (int e = 0; e < 4; ++e) {
                const int idx = base + e;
                const int j = idx / 3;
                const int k = idx - j * 3;
                sm[k    ][j] = f1[e];
                sm[3 + k][j] = f2[e];
                sm[6 + k][j] = f3[e];
            }
        }
        if (threadIdx.x < 48) sp[threadIdx.x] = xyz[pbase * 3 + threadIdx.x];
    }
    __syncthreads();

    const int chunk = threadIdx.x & 31;
    const int quad  = threadIdx.x >> 5;

    float px[4], py[4], pz[4];
    float bestD[4];
    int   bestT[4];
    #pragma unroll
    for (int k = 0; k < 4; ++k) {
        px[k] = sp[(quad * 4 + k) * 3 + 0];
        py[k] = sp[(quad * 4 + k) * 3 + 1];
        pz[k] = sp[(quad * 4 + k) * 3 + 2];
        bestD[k] = INFINITY;
        bestT[k] = 0x7fffffff;
    }

    #pragma unroll 2
    for (int j = 0; j < 16; ++j) {
        const int t = j * 32 + chunk;

        const float ax = sm[0][t], ay = sm[1][t], az = sm[2][t];
        const float bx = sm[3][t], by = sm[4][t], bz = sm[5][t];
        const float cx = sm[6][t], cy = sm[7][t], cz = sm[8][t];

        // Per-triangle setup, amortized over 4 points.
        const float abx = bx - ax, aby = by - ay, abz = bz - az;
        const float acx = cx - ax, acy = cy - ay, acz = cz - az;
        const float cbx = cx - bx, cby = cy - by, cbz = cz - bz;
        const float e1 = fmaf(abx, abx, fmaf(aby, aby, abz * abz));
        const float e2 = fmaf(abx, acx, fmaf(aby, acy, abz * acz));
        const float e3 = fmaf(acx, acx, fmaf(acy, acy, acz * acz));
        const float cb2 = fmaf(cbx, cbx, fmaf(cby, cby, cbz * cbz));
        const float f1  = e1 - e2;                      // for u1 = (d2-d1)+f1
        const float denom = fmaf(e1, e3, -(e2 * e2));   // |ab x ac|^2
        const float r_e1 = frcp(e1);
        const float r_e3 = frcp(e3);
        const float r_cb = frcp(cb2);
        const float r_dn = frcp(denom);

        #pragma unroll
        for (int k = 0; k < 4; ++k) {
            const float apx = px[k] - ax, apy = py[k] - ay, apz = pz[k] - az;
            const float d1 = fmaf(abx, apx, fmaf(aby, apy, abz * apz));
            const float d2 = fmaf(acx, apx, fmaf(acy, apy, acz * apz));

            // --- segment AB ---
            const float tA = fminf(fmaxf(d1 * r_e1, 0.f), 1.f);
            const float ax1 = fmaf(-tA, abx, apx);
            const float ay1 = fmaf(-tA, aby, apy);
            const float az1 = fmaf(-tA, abz, apz);
            const float dAB = fmaf(ax1, ax1, fmaf(ay1, ay1, az1 * az1));

            // --- segment AC ---
            const float tC = fminf(fmaxf(d2 * r_e3, 0.f), 1.f);
            const float cx1 = fmaf(-tC, acx, apx);
            const float cy1 = fmaf(-tC, acy, apy);
            const float cz1 = fmaf(-tC, acz, apz);
            const float dAC = fmaf(cx1, cx1, fmaf(cy1, cy1, cz1 * cz1));

            // --- segment BC ---  (bp = ap - ab; u1 = (d2-d1)+f1 = cb.bp)
            const float bpx = apx - abx, bpy = apy - aby, bpz = apz - abz;
            const float u1 = (d2 - d1) + f1;
            const float tB = fminf(fmaxf(u1 * r_cb, 0.f), 1.f);
            const float bx1 = fmaf(-tB, cbx, bpx);
            const float by1 = fmaf(-tB, cby, bpy);
            const float bz1 = fmaf(-tB, cbz, bpz);
            const float dBC = fmaf(bx1, bx1, fmaf(by1, by1, bz1 * bz1));

            // --- face (valid only if projection inside) ---
            const float vb = fmaf(e3, d1, -(e2 * d2));
            const float vc = fmaf(e1, d2, -(e2 * d1));
            const float va = denom - vb - vc;
            const float v = vb * r_dn;
            const float w = vc * r_dn;
            const float fx1 = fmaf(-w, acx, fmaf(-v, abx, apx));
            const float fy1 = fmaf(-w, acy, fmaf(-v, aby, apy));
            const float fz1 = fmaf(-w, acz, fmaf(-v, abz, apz));
            const float dF  = fmaf(fx1, fx1, fmaf(fy1, fy1, fz1 * fz1));
            const bool inside = (va >= 0.f) & (vb >= 0.f) & (vc >= 0.f);
            const float dFc = inside ? dF : INFINITY;   // NaN vb/vc -> excluded

            const float dEdge = fminf(fminf(dAB, dAC), dBC);
            const float d2s   = fminf(dEdge, dFc);

            if (d2s < bestD[k]) {   // t strictly increases -> first-win ok
                bestD[k] = d2s;
                bestT[k] = t;
            }
        }
    }

    // Lexicographic (dist, index) butterfly reduction across the 32 chunks.
    #pragma unroll
    for (int off = 1; off < 32; off <<= 1) {
        #pragma unroll
        for (int k = 0; k < 4; ++k) {
            float dO = __shfl_xor_sync(0xffffffffu, bestD[k], off);
            int   tO = __shfl_xor_sync(0xffffffffu, bestT[k], off);
            if (dO < bestD[k] || (dO == bestD[k] && tO < bestT[k])) {
                bestD[k] = dO;
                bestT[k] = tO;
            }
        }
    }

    if (chunk == 0) {
        #pragma unroll
        for (int k = 0; k < 4; ++k) {
            const int g = pbase + quad * 4 + k;
            const int t = bestT[k];
            const int r = region_of(px[k], py[k], pz[k],
                                    sm[0][t], sm[1][t], sm[2][t],
                                    sm[3][t], sm[4][t], sm[5][t],
                                    sm[6][t], sm[7][t], sm[8][t]);
            out[g]          = bestD[k];
            out[BN + g]     = (float)r;
            out[2 * BN + g] = (float)t;
        }
    }
}

extern "C" void kernel_launch(void* const* d_in, const int* in_sizes, int n_in,
                              void* d_out, int out_size)
{
    const float* xyz  = (const float*)d_in[0];
    const float* tri1 = (const float*)d_in[1];
    const float* tri2 = (const float*)d_in[2];
    const float* tri3 = (const float*)d_in[3];
    float* out = (float*)d_out;

    dim3 grid(BN / 16);   // 1024 CTAs
    dim3 block(128);
    tridist_kernel<<<grid, block>>>(xyz, tri1, tri2, tri3, out);
}